// round 4
// baseline (speedup 1.0000x reference)
#include <cuda_runtime.h>
#include <stdint.h>

// WeightedHashEmbedding, two-pass L2-phased variant:
//   out[b, d] = (1/32) * sum_{c=0..31} table[idx0[b,c], d] * weights[idx1[b,c]]
//
// Pass 0 accumulates chunks whose table row is in [0, HALF)   -> raw sum to out
// Pass 1 accumulates chunks whose table row is in [HALF, ROWS), adds out, /32
//
// Rationale: per-pass table compulsory footprint (~82 MB) fits L2 (126 MB),
// so the ~368K repeated row draws hit L2 instead of DRAM.

#define B_ROWS   32768
#define N_CHUNKS 32
#define DIM      64
#define HALF     524288

__device__ __forceinline__ uint64_t mk_evict_last_policy() {
    uint64_t pol;
    asm volatile("createpolicy.fractional.L2::evict_last.b64 %0, 1.0;"
                 : "=l"(pol));
    return pol;
}

__device__ __forceinline__ float2 ldg_table(const float2* p, uint64_t pol) {
    float2 v;
    asm volatile("ld.global.nc.L2::cache_hint.v2.f32 {%0,%1}, [%2], %3;"
                 : "=f"(v.x), "=f"(v.y) : "l"(p), "l"(pol));
    return v;
}

template <int PASS>
__global__ void __launch_bounds__(256)
whe_pass_kernel(const float* __restrict__ table,
                const float* __restrict__ weights,
                const int*   __restrict__ idx0,
                const int*   __restrict__ idx1,
                float2*      __restrict__ out)
{
    const int warps_per_block = blockDim.x >> 5;
    const int b    = blockIdx.x * warps_per_block + (threadIdx.x >> 5);
    const int lane = threadIdx.x & 31;
    if (b >= B_ROWS) return;

    // Coalesced index preload: lane c holds chunk c's indices.
    const int i0 = idx0[b * N_CHUNKS + lane];
    const int i1 = idx1[b * N_CHUNKS + lane];

    const uint64_t pol = mk_evict_last_policy();

    float2 acc;
    if (PASS == 0) {
        acc = make_float2(0.0f, 0.0f);
    } else {
        acc = out[b * 32 + lane];   // partial sum from pass 0
    }

    #pragma unroll
    for (int c = 0; c < N_CHUNKS; ++c) {
        const int t = __shfl_sync(0xffffffffu, i0, c);
        // Warp-uniform predicate: whole warp takes or skips the chunk together.
        const bool take = (PASS == 0) ? (t < HALF) : (t >= HALF);
        if (take) {
            const int w = __shfl_sync(0xffffffffu, i1, c);
            // Broadcast scalar weight: one 32B sector per chunk, streaming.
            const float  wv = __ldcs(weights + (uint32_t)w);
            const float2 v  = ldg_table(((const float2*)(table + (size_t)t * DIM)) + lane, pol);
            acc.x = fmaf(v.x, wv, acc.x);
            acc.y = fmaf(v.y, wv, acc.y);
        }
    }

    if (PASS == 1) {
        acc.x *= (1.0f / N_CHUNKS);
        acc.y *= (1.0f / N_CHUNKS);
    }
    out[b * 32 + lane] = acc;
}

extern "C" void kernel_launch(void* const* d_in, const int* in_sizes, int n_in,
                              void* d_out, int out_size)
{
    const float* table   = (const float*)d_in[0];
    const float* weights = (const float*)d_in[1];
    const int*   idx0    = (const int*)d_in[2];
    const int*   idx1    = (const int*)d_in[3];
    float2*      out     = (float2*)d_out;

    const int threads = 256;                       // 8 warps -> 8 rows / block
    const int blocks  = B_ROWS / (threads / 32);   // 4096
    whe_pass_kernel<0><<<blocks, threads>>>(table, weights, idx0, idx1, out);
    whe_pass_kernel<1><<<blocks, threads>>>(table, weights, idx0, idx1, out);
}

// round 5
// speedup vs baseline: 1.0268x; 1.0268x over previous
#include <cuda_runtime.h>
#include <stdint.h>

// WeightedHashEmbedding, two-pass L2-phased, 2 rows/warp:
//   out[b, d] = (1/32) * sum_{c=0..31} table[idx0[b,c], d] * weights[idx1[b,c]]
//
// Pass 0: chunks with idx0 in [0, HALF)     -> raw partial sum to out
// Pass 1: chunks with idx0 in [HALF, ROWS)  -> += partial, * 1/32
//
// vs R4: NO cache-policy hints on table (test whether evict_last policy was
// what killed L2 retention), and each warp carries TWO output rows so ~32
// predicated loads stay in flight (R4 halved MLP and went latency-bound,
// DRAM% 74 -> 41).

#define B_ROWS   32768
#define N_CHUNKS 32
#define DIM      64
#define HALF     524288

template <int PASS>
__global__ void __launch_bounds__(256)
whe_pass_kernel(const float* __restrict__ table,
                const float* __restrict__ weights,
                const int*   __restrict__ idx0,
                const int*   __restrict__ idx1,
                float2*      __restrict__ out)
{
    const int warp = blockIdx.x * (blockDim.x >> 5) + (threadIdx.x >> 5);
    const int lane = threadIdx.x & 31;
    const int b0   = warp * 2;
    const int b1   = b0 + 1;

    // Coalesced index preload: lane c holds chunk c's indices for both rows.
    const int i0a = idx0[b0 * N_CHUNKS + lane];
    const int i1a = idx1[b0 * N_CHUNKS + lane];
    const int i0b = idx0[b1 * N_CHUNKS + lane];
    const int i1b = idx1[b1 * N_CHUNKS + lane];

    float2 acc0, acc1;
    if (PASS == 0) {
        acc0 = make_float2(0.0f, 0.0f);
        acc1 = make_float2(0.0f, 0.0f);
    } else {
        acc0 = out[b0 * 32 + lane];
        acc1 = out[b1 * 32 + lane];
    }

    #pragma unroll
    for (int c = 0; c < N_CHUNKS; ++c) {
        // Row b0, chunk c — predicate is warp-uniform (t broadcast to all lanes).
        {
            const int t = __shfl_sync(0xffffffffu, i0a, c);
            if ((PASS == 0) ? (t < HALF) : (t >= HALF)) {
                const int   w  = __shfl_sync(0xffffffffu, i1a, c);
                const float wv = __ldcs(weights + (uint32_t)w);   // streaming: no L2 pollution
                const float2 v = __ldg(((const float2*)(table + (size_t)t * DIM)) + lane);
                acc0.x = fmaf(v.x, wv, acc0.x);
                acc0.y = fmaf(v.y, wv, acc0.y);
            }
        }
        // Row b1, chunk c.
        {
            const int t = __shfl_sync(0xffffffffu, i0b, c);
            if ((PASS == 0) ? (t < HALF) : (t >= HALF)) {
                const int   w  = __shfl_sync(0xffffffffu, i1b, c);
                const float wv = __ldcs(weights + (uint32_t)w);
                const float2 v = __ldg(((const float2*)(table + (size_t)t * DIM)) + lane);
                acc1.x = fmaf(v.x, wv, acc1.x);
                acc1.y = fmaf(v.y, wv, acc1.y);
            }
        }
    }

    if (PASS == 1) {
        acc0.x *= (1.0f / N_CHUNKS);  acc0.y *= (1.0f / N_CHUNKS);
        acc1.x *= (1.0f / N_CHUNKS);  acc1.y *= (1.0f / N_CHUNKS);
    }
    out[b0 * 32 + lane] = acc0;
    out[b1 * 32 + lane] = acc1;
}

extern "C" void kernel_launch(void* const* d_in, const int* in_sizes, int n_in,
                              void* d_out, int out_size)
{
    const float* table   = (const float*)d_in[0];
    const float* weights = (const float*)d_in[1];
    const int*   idx0    = (const int*)d_in[2];
    const int*   idx1    = (const int*)d_in[3];
    float2*      out     = (float2*)d_out;

    const int threads = 256;                           // 8 warps, 2 rows/warp -> 16 rows/block
    const int blocks  = B_ROWS / 16;                   // 2048
    whe_pass_kernel<0><<<blocks, threads>>>(table, weights, idx0, idx1, out);
    whe_pass_kernel<1><<<blocks, threads>>>(table, weights, idx0, idx1, out);
}

// round 6
// speedup vs baseline: 1.7832x; 1.7367x over previous
#include <cuda_runtime.h>
#include <stdint.h>

// WeightedHashEmbedding, single-pass persistent-grid gather:
//   out[b, d] = (1/32) * sum_{c=0..31} table[idx0[b,c], d] * weights[idx1[b,c]]
//
// Byte floor (measured, zero L2 reuse on random 256B gathers):
//   table 268 MB + weights ~67 MB (64B DRAM granule) + idx 8 MB + out 8 MB.
// Strategy: saturate HBM continuously. Persistent grid (148 SMs x 4 blocks,
// grid-stride over rows) removes the ~7 wave transitions + block churn that
// left DRAM 26% idle in the one-row-per-warp launch.

#define B_ROWS   32768
#define N_CHUNKS 32
#define DIM      64
#define NUM_SMS  148
#define BLOCKS_PER_SM 4

__global__ void __launch_bounds__(256, BLOCKS_PER_SM)
whe_kernel(const float* __restrict__ table,
           const float* __restrict__ weights,
           const int*   __restrict__ idx0,
           const int*   __restrict__ idx1,
           float2*      __restrict__ out)
{
    const int lane        = threadIdx.x & 31;
    const int warp_global = blockIdx.x * (blockDim.x >> 5) + (threadIdx.x >> 5);
    const int total_warps = gridDim.x * (blockDim.x >> 5);   // 4736

    for (int b = warp_global; b < B_ROWS; b += total_warps) {
        // Coalesced index preload: lane c holds chunk c's indices.
        const int i0 = idx0[b * N_CHUNKS + lane];
        const int i1 = idx1[b * N_CHUNKS + lane];

        // All 32 weights fetched with one divergent streaming load
        // (off the accumulation critical path; evict-first keeps the
        // one-shot 32B sectors from occupying L2).
        const float wv_lane = __ldcs(weights + (uint32_t)i1);

        float2 acc = make_float2(0.0f, 0.0f);

        #pragma unroll
        for (int c = 0; c < N_CHUNKS; ++c) {
            const int   t  = __shfl_sync(0xffffffffu, i0, c);
            const float wv = __shfl_sync(0xffffffffu, wv_lane, c);
            const float2 v = __ldg(((const float2*)(table + (size_t)t * DIM)) + lane);
            acc.x = fmaf(v.x, wv, acc.x);
            acc.y = fmaf(v.y, wv, acc.y);
        }

        acc.x *= (1.0f / N_CHUNKS);
        acc.y *= (1.0f / N_CHUNKS);
        out[b * 32 + lane] = acc;
    }
}

extern "C" void kernel_launch(void* const* d_in, const int* in_sizes, int n_in,
                              void* d_out, int out_size)
{
    const float* table   = (const float*)d_in[0];
    const float* weights = (const float*)d_in[1];
    const int*   idx0    = (const int*)d_in[2];
    const int*   idx1    = (const int*)d_in[3];
    float2*      out     = (float2*)d_out;

    const int threads = 256;                       // 8 warps/block
    const int blocks  = NUM_SMS * BLOCKS_PER_SM;   // 592 — exactly resident
    whe_kernel<<<blocks, threads>>>(table, weights, idx0, idx1, out);
}

// round 7
// speedup vs baseline: 1.7951x; 1.0067x over previous
#include <cuda_runtime.h>
#include <stdint.h>

// WeightedHashEmbedding, persistent-grid, software-pipelined:
//   out[b, d] = (1/32) * sum_{c=0..31} table[idx0[b,c], d] * weights[idx1[b,c]]
//
// At the measured DRAM random-access ceiling (~5.9 TB/s, 74% active).
// This round shaves non-table traffic: streaming stores for out (no
// write-allocate), streaming loads for the one-shot idx arrays, and
// prefetches the next row's idx+weight gather under the current row's
// 32 table loads.

#define B_ROWS   32768
#define N_CHUNKS 32
#define DIM      64
#define NUM_SMS  148
#define BLOCKS_PER_SM 4

__device__ __forceinline__ void stcs_f2(float2* p, float2 v) {
    asm volatile("st.global.cs.v2.f32 [%0], {%1,%2};" :: "l"(p), "f"(v.x), "f"(v.y));
}

__global__ void __launch_bounds__(256, BLOCKS_PER_SM)
whe_kernel(const float* __restrict__ table,
           const float* __restrict__ weights,
           const int*   __restrict__ idx0,
           const int*   __restrict__ idx1,
           float2*      __restrict__ out)
{
    const int lane        = threadIdx.x & 31;
    const int warp_global = blockIdx.x * (blockDim.x >> 5) + (threadIdx.x >> 5);
    const int total_warps = gridDim.x * (blockDim.x >> 5);   // 4736

    int b = warp_global;

    // Prologue: load row b's indices + weight (lane c holds chunk c).
    int   i0 = 0;
    float wv = 0.0f;
    if (b < B_ROWS) {
        i0 = __ldcs(idx0 + b * N_CHUNKS + lane);
        const int i1 = __ldcs(idx1 + b * N_CHUNKS + lane);
        // Divergent one-shot gather; fold the mean's 1/32 in here.
        wv = __ldcs(weights + (uint32_t)i1) * (1.0f / N_CHUNKS);
    }

    while (b < B_ROWS) {
        const int   cur_i0 = i0;
        const float cur_wv = wv;
        const int   bn     = b + total_warps;

        // Prefetch next row's indices + weight under this row's table loads.
        if (bn < B_ROWS) {
            i0 = __ldcs(idx0 + bn * N_CHUNKS + lane);
            const int i1 = __ldcs(idx1 + bn * N_CHUNKS + lane);
            wv = __ldcs(weights + (uint32_t)i1) * (1.0f / N_CHUNKS);
        }

        float2 acc = make_float2(0.0f, 0.0f);

        #pragma unroll
        for (int c = 0; c < N_CHUNKS; ++c) {
            const int   t = __shfl_sync(0xffffffffu, cur_i0, c);
            const float w = __shfl_sync(0xffffffffu, cur_wv, c);
            const float2 v = __ldg(((const float2*)(table + (size_t)t * DIM)) + lane);
            acc.x = fmaf(v.x, w, acc.x);
            acc.y = fmaf(v.y, w, acc.y);
        }

        // Streaming store: out is written once, never re-read.
        stcs_f2(out + b * 32 + lane, acc);

        b = bn;
    }
}

extern "C" void kernel_launch(void* const* d_in, const int* in_sizes, int n_in,
                              void* d_out, int out_size)
{
    const float* table   = (const float*)d_in[0];
    const float* weights = (const float*)d_in[1];
    const int*   idx0    = (const int*)d_in[2];
    const int*   idx1    = (const int*)d_in[3];
    float2*      out     = (float2*)d_out;

    const int threads = 256;                       // 8 warps/block
    const int blocks  = NUM_SMS * BLOCKS_PER_SM;   // 592 — exactly resident
    whe_kernel<<<blocks, threads>>>(table, weights, idx0, idx1, out);
}